// round 17
// baseline (speedup 1.0000x reference)
#include <cuda_runtime.h>
#include <cuda_fp16.h>
#include <math.h>
#include <stdint.h>

// Problem constants
#define B_  4
#define T_  1024
#define D_  2048
#define KV_ 512
#define NH_ 32
#define NKV_ 8
#define HD_ 64
#define MROWS (B_*T_)   // 4096

// Scratch (static device globals; no runtime allocation)
__device__ float  g_Q[MROWS * D_];      // fp32 Q projection (pre-rope)
__device__ float  g_KV[MROWS * 1024];   // fp32 fused K|V projection (pre-rope)
__device__ float  g_KN[B_ * NKV_ * T_]; // 0.5*||k||^2 / 8 per key (from fp16-rounded k)
__device__ float  g_cosT[T_ * 32];      // rope cos table [tpos][i]
__device__ float  g_sinT[T_ * 32];      // rope sin table [tpos][i]
__device__ __half g_Qh[MROWS * D_];     // rope'd, scaled 1/8, fp16
__device__ __half g_Kh[MROWS * KV_];    // rope'd K, fp16
__device__ __half g_Vt[B_ * NKV_ * HD_ * T_]; // V transposed per head: [b][kvh][d][t]
__device__ __half g_Yh[MROWS * D_];     // attention out, (b,t,h*hd), fp16
__device__ __half g_xh[MROWS * D_];     // fp16 x
// fp16 TRANSPOSED weights ([N][K] K-major) for GEMM B operand
__device__ __half g_Wqt[D_ * D_];
__device__ __half g_Wkvt[1024 * D_];    // rows 0..511 = Wk^T, 512..1023 = Wv^T
__device__ __half g_Wot[D_ * D_];

// ---------------------------------------------------------------------------
// helpers
// ---------------------------------------------------------------------------
__device__ __forceinline__ uint32_t pack_h2(float a, float b) {
    __half2 h = __floats2half2_rn(a, b);   // low = a, high = b
    return *(uint32_t*)&h;
}

__device__ __forceinline__ void mma_f16(float c[4],
    uint32_t a0, uint32_t a1, uint32_t a2, uint32_t a3,
    uint32_t b0, uint32_t b1)
{
    asm volatile(
        "mma.sync.aligned.m16n8k16.row.col.f32.f16.f16.f32 "
        "{%0,%1,%2,%3}, {%4,%5,%6,%7}, {%8,%9}, {%0,%1,%2,%3};"
        : "+f"(c[0]), "+f"(c[1]), "+f"(c[2]), "+f"(c[3])
        : "r"(a0), "r"(a1), "r"(a2), "r"(a3), "r"(b0), "r"(b1));
}

__device__ __forceinline__ void cp_async16(uint32_t smem, const void* gmem) {
    asm volatile("cp.async.cg.shared.global [%0], [%1], 16;" :: "r"(smem), "l"(gmem));
}
__device__ __forceinline__ void cp_commit() {
    asm volatile("cp.async.commit_group;");
}
template<int N> __device__ __forceinline__ void cp_wait() {
    asm volatile("cp.async.wait_group %0;" :: "n"(N));
}
__device__ __forceinline__ uint32_t smem_u32(const void* p) {
    return (uint32_t)__cvta_generic_to_shared(p);
}

// ---------------------------------------------------------------------------
// fp16 GEMM (unchanged from round 14/15 — at the mma.sync issue ceiling)
// ---------------------------------------------------------------------------
#define GH_STRIDE 20
#define GH_ELEMS (2 * 128 * GH_STRIDE)
#define GH_SMEM_BYTES (2 * GH_ELEMS * 4)     // 40960

__global__ __launch_bounds__(256) void gemm_f16(
    const __half* __restrict__ A, const __half* __restrict__ Bt,
    float* __restrict__ C, int N, int K)
{
    extern __shared__ uint32_t smu[];
    uint32_t* As = smu;
    uint32_t* Bs = smu + GH_ELEMS;

    const int tid  = threadIdx.x;
    const int lane = tid & 31;
    const int wid  = tid >> 5;
    const int g    = lane >> 2;
    const int t    = lane & 3;
    const int wm   = (wid & 1) * 64;
    const int wn   = (wid >> 1) * 32;
    const int bx = blockIdx.x, by = blockIdx.y;

    float acc[4][4][4];
#pragma unroll
    for (int mi = 0; mi < 4; mi++)
#pragma unroll
        for (int nj = 0; nj < 4; nj++)
#pragma unroll
            for (int e = 0; e < 4; e++) acc[mi][nj][e] = 0.f;

    const __half* Ab = A  + (size_t)(by * 128) * K;
    const __half* Bb = Bt + (size_t)(bx * 128) * K;

    const int r  = tid >> 1;
    const int cu = (tid & 1) * 8;

    const int niter = K >> 5;

#define GH_IDX(s, rr, cc) ((((s) * 128) + (rr)) * GH_STRIDE + (cc))

    cp_async16(smem_u32(&As[GH_IDX(0, r, cu)]),     Ab + (size_t)r * K + cu * 2);
    cp_async16(smem_u32(&As[GH_IDX(0, r, cu + 4)]), Ab + (size_t)r * K + cu * 2 + 8);
    cp_async16(smem_u32(&Bs[GH_IDX(0, r, cu)]),     Bb + (size_t)r * K + cu * 2);
    cp_async16(smem_u32(&Bs[GH_IDX(0, r, cu + 4)]), Bb + (size_t)r * K + cu * 2 + 8);
    cp_commit();

    for (int it = 0; it < niter; it++) {
        const int cb = it & 1;
        if (it + 1 < niter) {
            const int k0 = (it + 1) << 5;
            const int nb = cb ^ 1;
            cp_async16(smem_u32(&As[GH_IDX(nb, r, cu)]),     Ab + (size_t)r * K + k0 + cu * 2);
            cp_async16(smem_u32(&As[GH_IDX(nb, r, cu + 4)]), Ab + (size_t)r * K + k0 + cu * 2 + 8);
            cp_async16(smem_u32(&Bs[GH_IDX(nb, r, cu)]),     Bb + (size_t)r * K + k0 + cu * 2);
            cp_async16(smem_u32(&Bs[GH_IDX(nb, r, cu + 4)]), Bb + (size_t)r * K + k0 + cu * 2 + 8);
            cp_commit();
            cp_wait<1>();
        } else {
            cp_wait<0>();
        }
        __syncthreads();

#pragma unroll
        for (int ks = 0; ks < 2; ks++) {
            const int kc = ks * 8;
            uint32_t a[4][4];
#pragma unroll
            for (int mi = 0; mi < 4; mi++) {
                const int r0 = wm + mi * 16 + g;
                a[mi][0] = As[GH_IDX(cb, r0,     kc + t)];
                a[mi][1] = As[GH_IDX(cb, r0 + 8, kc + t)];
                a[mi][2] = As[GH_IDX(cb, r0,     kc + t + 4)];
                a[mi][3] = As[GH_IDX(cb, r0 + 8, kc + t + 4)];
            }
            uint32_t b[4][2];
#pragma unroll
            for (int nj = 0; nj < 4; nj++) {
                const int n0 = wn + nj * 8 + g;
                b[nj][0] = Bs[GH_IDX(cb, n0, kc + t)];
                b[nj][1] = Bs[GH_IDX(cb, n0, kc + t + 4)];
            }
#pragma unroll
            for (int mi = 0; mi < 4; mi++)
#pragma unroll
                for (int nj = 0; nj < 4; nj++)
                    mma_f16(acc[mi][nj], a[mi][0], a[mi][1], a[mi][2], a[mi][3],
                            b[nj][0], b[nj][1]);
        }
        __syncthreads();
    }

#pragma unroll
    for (int mi = 0; mi < 4; mi++) {
        const int r0 = by * 128 + wm + mi * 16 + g;
#pragma unroll
        for (int nj = 0; nj < 4; nj++) {
            const int col = bx * 128 + wn + nj * 8 + 2 * t;
            *(float2*)(C + (size_t)r0 * N + col)       = make_float2(acc[mi][nj][0], acc[mi][nj][1]);
            *(float2*)(C + (size_t)(r0 + 8) * N + col) = make_float2(acc[mi][nj][2], acc[mi][nj][3]);
        }
    }
}

// ---------------------------------------------------------------------------
// Prep kernels
// ---------------------------------------------------------------------------
__global__ void cvt_half_kernel(const float* __restrict__ s, __half* __restrict__ d, int n2)
{
    int i = blockIdx.x * blockDim.x + threadIdx.x;
    if (i < n2) {
        float2 v = ((const float2*)s)[i];
        ((__half2*)d)[i] = __floats2half2_rn(v.x, v.y);
    }
}

// rope table: same formula as the old per-thread computation (bit-identical c,s)
__global__ void rope_table_kernel()
{
    int idx = blockIdx.x * 256 + threadIdx.x;     // 32768
    int tpos = idx >> 5, i = idx & 31;
    float inv = 1.0f / powf(10000.0f, (float)i * (1.0f / 32.0f));
    float s, c;
    sincosf((float)tpos * inv, &s, &c);
    g_cosT[idx] = c;
    g_sinT[idx] = s;
}

// merged Wq/Wo transpose: z=0 -> Wq^T, z=1 -> Wo^T  (D x D each)
__global__ void transpose_qo_kernel(const float* __restrict__ Wq,
                                    const float* __restrict__ Wo)
{
    __shared__ float s[32][33];
    const float* in = blockIdx.z ? Wo : Wq;
    __half* o = blockIdx.z ? g_Wot : g_Wqt;
    const int c0 = blockIdx.x * 32, r0 = blockIdx.y * 32;
    const int tx = threadIdx.x, ty = threadIdx.y;
#pragma unroll
    for (int i = 0; i < 4; i++)
        s[ty + 8 * i][tx] = in[(size_t)(r0 + ty + 8 * i) * D_ + c0 + tx];
    __syncthreads();
#pragma unroll
    for (int i = 0; i < 4; i++)
        o[(size_t)(c0 + ty + 8 * i) * D_ + r0 + tx] = __float2half_rn(s[tx][ty + 8 * i]);
}

// merged Wk/Wv transpose: z=0 -> Wk^T rows 0..511, z=1 -> Wv^T rows 512..1023
__global__ void transpose_wkv_kernel(const float* __restrict__ Wk,
                                     const float* __restrict__ Wv,
                                     __half* __restrict__ out)
{
    __shared__ float s[32][33];
    const float* in = blockIdx.z ? Wv : Wk;
    __half* o = out + (size_t)blockIdx.z * KV_ * D_;
    const int c0 = blockIdx.x * 32, r0 = blockIdx.y * 32;
    const int tx = threadIdx.x, ty = threadIdx.y;
#pragma unroll
    for (int i = 0; i < 4; i++)
        s[ty + 8 * i][tx] = in[(size_t)(r0 + ty + 8 * i) * KV_ + c0 + tx];
    __syncthreads();
#pragma unroll
    for (int i = 0; i < 4; i++)
        o[(size_t)(c0 + ty + 8 * i) * D_ + r0 + tx] = __float2half_rn(s[tx][ty + 8 * i]);
}

// ---------------------------------------------------------------------------
// RoPE for Q (table-based): f32 g_Q -> f16 g_Qh, scaled by 0.125.
// ---------------------------------------------------------------------------
__global__ void rope_q_kernel()
{
    const int row  = blockIdx.x;
    const int tpos = row & (T_ - 1);
    const int h = threadIdx.x >> 5;
    const int i = threadIdx.x & 31;

    float c = g_cosT[tpos * 32 + i];
    float s = g_sinT[tpos * 32 + i];

    const float* p = g_Q + (size_t)row * D_ + h * HD_;
    __half* o = g_Qh + (size_t)row * D_ + h * HD_;
    float x1 = p[i], x2 = p[i + 32];
    o[i]      = __float2half_rn((x1 * c - x2 * s) * 0.125f);
    o[i + 32] = __float2half_rn((x2 * c + x1 * s) * 0.125f);
}

// ---------------------------------------------------------------------------
// RoPE for K (table-based) + kn from f16-rounded k + V -> transposed f16.
// ---------------------------------------------------------------------------
__global__ void rope_k_kernel()
{
    const int row  = blockIdx.x;
    const int tpos = row & (T_ - 1);
    const int h = threadIdx.x >> 5;
    const int i = threadIdx.x & 31;

    float c = g_cosT[tpos * 32 + i];
    float s = g_sinT[tpos * 32 + i];

    const float* p = g_KV + (size_t)row * 1024 + h * HD_;
    __half* o = g_Kh + (size_t)row * KV_ + h * HD_;
    float x1 = p[i], x2 = p[i + 32];
    __half h1 = __float2half_rn(x1 * c - x2 * s);
    __half h2 = __float2half_rn(x2 * c + x1 * s);
    o[i]      = h1;
    o[i + 32] = h2;

    float o1 = __half2float(h1), o2 = __half2float(h2);
    float nsq = o1 * o1 + o2 * o2;
#pragma unroll
    for (int off = 16; off; off >>= 1)
        nsq += __shfl_xor_sync(0xffffffffu, nsq, off);
    const int bb = row / T_;
    if (i == 0)
        g_KN[(bb * NKV_ + h) * T_ + tpos] = nsq * 0.0625f;  // 0.5/8

    const int j = threadIdx.x;
#pragma unroll
    for (int u = 0; u < 2; u++) {
        int col = j + u * 256;               // 0..511
        int kvh = col >> 6, dd = col & 63;
        float v = g_KV[(size_t)row * 1024 + 512 + col];
        g_Vt[(size_t)((bb * NKV_ + kvh) * HD_ + dd) * T_ + tpos] = __float2half_rn(v);
    }
}

// ---------------------------------------------------------------------------
// Flash attention, GQA-shared K/V. CTA = (b, kvh, 64-row q-tile).
// 256 thr = 8 warps: warp w -> head hg = w>>2? no: hg = w>>1 (4 heads),
// sub = w&1 (rows sub*32..sub*32+31), two 16-row mma groups p=0,1.
// K/V tiles of 64 keys staged ONCE per tile for all 4 heads.
// grid = (T/64, B*NKV); heavy (long causal window) blocks first.
// ---------------------------------------------------------------------------
__global__ __launch_bounds__(256) void flash_f16_kernel()
{
    __shared__ uint32_t S[4 * 64 * 36];   // Q stage (4 heads x 64 x 36); later Ks=S, Vs=S+2304
    __shared__ float kns[64];
    uint32_t* Ks = S;
    uint32_t* Vs = S + 2304;

    const int byi = blockIdx.y;          // 0..31
    const int bb  = byi >> 3;
    const int kvh = byi & 7;
    const int qb  = gridDim.x - 1 - blockIdx.x;   // heavy first
    const int q0  = qb << 6;
    const int tid = threadIdx.x;
    const int w   = tid >> 5;
    const int lane = tid & 31;
    const int g   = lane >> 2;
    const int t   = lane & 3;
    const int hg  = w >> 1;              // head-in-group 0..3
    const int sub = w & 1;               // row half 0/1
    const int h   = kvh * 4 + hg;

    // ---- stage Q for all 4 heads: thread -> (head tid>>6, row tid&63) ----
    {
        const int hh = tid >> 6, row = tid & 63;
        const __half* qp = g_Qh + (size_t)(bb * T_ + q0 + row) * D_ + (kvh * 4 + hh) * HD_;
        uint32_t* dst = &S[hh * 2304 + row * 36];
#pragma unroll
        for (int u = 0; u < 8; u++)
            *(uint4*)&dst[4 * u] = ((const uint4*)qp)[u];
    }
    __syncthreads();

    // ---- extract A-fragments for both 16-row groups ----
    uint32_t aq[2][4][4];
#pragma unroll
    for (int p = 0; p < 2; p++) {
        const int qr = sub * 32 + p * 16 + g;
        const uint32_t* Qs = &S[hg * 2304];
#pragma unroll
        for (int ks = 0; ks < 4; ks++) {
            aq[p][ks][0] = Qs[qr * 36 + ks * 8 + t];
            aq[p][ks][1] = Qs[(qr + 8) * 36 + ks * 8 + t];
            aq[p][ks][2] = Qs[qr * 36 + ks * 8 + t + 4];
            aq[p][ks][3] = Qs[(qr + 8) * 36 + ks * 8 + t + 4];
        }
    }
    __syncthreads();

    float oa[2][8][4];
#pragma unroll
    for (int p = 0; p < 2; p++)
#pragma unroll
        for (int nd = 0; nd < 8; nd++)
#pragma unroll
            for (int e = 0; e < 4; e++) oa[p][nd][e] = 0.f;
    float fm0[2] = {-1e30f, -1e30f}, fm1[2] = {-1e30f, -1e30f};
    float fl0[2] = {0.f, 0.f},       fl1[2] = {0.f, 0.f};

    const int ntiles = qb + 1;
    const int lr2 = tid >> 2, lcu2 = (tid & 3) * 8;

    for (int kt = 0; kt < ntiles; kt++) {
        const int kbase = kt << 6;
        const bool needmask = (kt == qb);

        __syncthreads();
        {
            const __half* kp = g_Kh + (size_t)(bb * T_ + kbase + lr2) * KV_ + kvh * HD_ + lcu2 * 2;
            *(uint4*)&Ks[lr2 * 36 + lcu2]     = ((const uint4*)kp)[0];
            *(uint4*)&Ks[lr2 * 36 + lcu2 + 4] = ((const uint4*)kp)[1];
            const __half* vp = g_Vt + (size_t)((bb * NKV_ + kvh) * HD_ + lr2) * T_ + kbase + lcu2 * 2;
            *(uint4*)&Vs[lr2 * 36 + lcu2]     = ((const uint4*)vp)[0];
            *(uint4*)&Vs[lr2 * 36 + lcu2 + 4] = ((const uint4*)vp)[1];
        }
        if (tid < 64)
            kns[tid] = g_KN[(bb * NKV_ + kvh) * T_ + kbase + tid];
        __syncthreads();

#pragma unroll
        for (int p = 0; p < 2; p++) {
            const int qr = sub * 32 + p * 16 + g;

            // ---- S = Q K^T ----
            float sc[8][4];
#pragma unroll
            for (int nj = 0; nj < 8; nj++)
#pragma unroll
                for (int e = 0; e < 4; e++) sc[nj][e] = 0.f;
#pragma unroll
            for (int ks = 0; ks < 4; ks++) {
#pragma unroll
                for (int nj = 0; nj < 8; nj++) {
                    const int n0 = nj * 8 + g;
                    uint32_t b0 = Ks[n0 * 36 + ks * 8 + t];
                    uint32_t b1 = Ks[n0 * 36 + ks * 8 + t + 4];
                    mma_f16(sc[nj], aq[p][ks][0], aq[p][ks][1], aq[p][ks][2], aq[p][ks][3], b0, b1);
                }
            }

            // ---- conformal term + causal mask + row maxes ----
            float mr0 = -1e30f, mr1 = -1e30f;
#pragma unroll
            for (int nj = 0; nj < 8; nj++) {
                const int c0 = nj * 8 + 2 * t, c1 = c0 + 1;
                float kn0 = kns[c0], kn1 = kns[c1];
                sc[nj][0] -= kn0; sc[nj][1] -= kn1;
                sc[nj][2] -= kn0; sc[nj][3] -= kn1;
                if (needmask) {
                    const int lim0 = qr, lim1 = qr + 8;
                    if (c0 > lim0) sc[nj][0] = -1e30f;
                    if (c1 > lim0) sc[nj][1] = -1e30f;
                    if (c0 > lim1) sc[nj][2] = -1e30f;
                    if (c1 > lim1) sc[nj][3] = -1e30f;
                }
                mr0 = fmaxf(mr0, fmaxf(sc[nj][0], sc[nj][1]));
                mr1 = fmaxf(mr1, fmaxf(sc[nj][2], sc[nj][3]));
            }
            mr0 = fmaxf(mr0, __shfl_xor_sync(0xffffffffu, mr0, 1));
            mr0 = fmaxf(mr0, __shfl_xor_sync(0xffffffffu, mr0, 2));
            mr1 = fmaxf(mr1, __shfl_xor_sync(0xffffffffu, mr1, 1));
            mr1 = fmaxf(mr1, __shfl_xor_sync(0xffffffffu, mr1, 2));

            const float mn0 = fmaxf(fm0[p], mr0), mn1 = fmaxf(fm1[p], mr1);
            const float cor0 = __expf(fm0[p] - mn0), cor1 = __expf(fm1[p] - mn1);
            fm0[p] = mn0; fm1[p] = mn1;

            // ---- P = exp(S - m), row sums ----
            float ps0 = 0.f, ps1 = 0.f;
#pragma unroll
            for (int nj = 0; nj < 8; nj++) {
                sc[nj][0] = __expf(sc[nj][0] - mn0);
                sc[nj][1] = __expf(sc[nj][1] - mn0);
                sc[nj][2] = __expf(sc[nj][2] - mn1);
                sc[nj][3] = __expf(sc[nj][3] - mn1);
                ps0 += sc[nj][0] + sc[nj][1];
                ps1 += sc[nj][2] + sc[nj][3];
            }
            ps0 += __shfl_xor_sync(0xffffffffu, ps0, 1);
            ps0 += __shfl_xor_sync(0xffffffffu, ps0, 2);
            ps1 += __shfl_xor_sync(0xffffffffu, ps1, 1);
            ps1 += __shfl_xor_sync(0xffffffffu, ps1, 2);
            fl0[p] = fl0[p] * cor0 + ps0;
            fl1[p] = fl1[p] * cor1 + ps1;

            // ---- rescale O ----
#pragma unroll
            for (int nd = 0; nd < 8; nd++) {
                oa[p][nd][0] *= cor0; oa[p][nd][1] *= cor0;
                oa[p][nd][2] *= cor1; oa[p][nd][3] *= cor1;
            }

            // ---- O += P V : C-frag feeds A-frag directly ----
#pragma unroll
            for (int j = 0; j < 4; j++) {
                uint32_t a0 = pack_h2(sc[2 * j][0],     sc[2 * j][1]);
                uint32_t a1 = pack_h2(sc[2 * j][2],     sc[2 * j][3]);
                uint32_t a2 = pack_h2(sc[2 * j + 1][0], sc[2 * j + 1][1]);
                uint32_t a3 = pack_h2(sc[2 * j + 1][2], sc[2 * j + 1][3]);
#pragma unroll
                for (int nd = 0; nd < 8; nd++) {
                    const int n0 = nd * 8 + g;
                    uint32_t b0 = Vs[n0 * 36 + j * 8 + t];
                    uint32_t b1 = Vs[n0 * 36 + j * 8 + t + 4];
                    mma_f16(oa[p][nd], a0, a1, a2, a3, b0, b1);
                }
            }
        }
    }

    // ---- normalize + write fp16 Y ----
#pragma unroll
    for (int p = 0; p < 2; p++) {
        const float il0 = 1.0f / fl0[p], il1 = 1.0f / fl1[p];
        const int qrow = q0 + sub * 32 + p * 16 + g;
        __half* yp0 = g_Yh + (size_t)(bb * T_ + qrow) * D_ + h * HD_;
        __half* yp1 = yp0 + (size_t)8 * D_;
#pragma unroll
        for (int nd = 0; nd < 8; nd++) {
            const int col = nd * 8 + 2 * t;
            *(__half2*)(yp0 + col) = __floats2half2_rn(oa[p][nd][0] * il0, oa[p][nd][1] * il0);
            *(__half2*)(yp1 + col) = __floats2half2_rn(oa[p][nd][2] * il1, oa[p][nd][3] * il1);
        }
    }
}

// ---------------------------------------------------------------------------
extern "C" void kernel_launch(void* const* d_in, const int* in_sizes, int n_in,
                              void* d_out, int out_size)
{
    const float* x  = (const float*)d_in[0];
    const float* Wq = (const float*)d_in[1];
    const float* Wk = (const float*)d_in[2];
    const float* Wv = (const float*)d_in[3];
    const float* Wo = (const float*)d_in[4];
    float* out = (float*)d_out;

    float *Q, *KV;
    __half *Qh, *Kh, *Vt, *Yh, *xh, *Wqt, *Wkvt, *Wot;
    cudaGetSymbolAddress((void**)&Q, g_Q);
    cudaGetSymbolAddress((void**)&KV, g_KV);
    cudaGetSymbolAddress((void**)&Qh, g_Qh);
    cudaGetSymbolAddress((void**)&Kh, g_Kh);
    cudaGetSymbolAddress((void**)&Vt, g_Vt);
    cudaGetSymbolAddress((void**)&Yh, g_Yh);
    cudaGetSymbolAddress((void**)&xh, g_xh);
    cudaGetSymbolAddress((void**)&Wqt, g_Wqt);
    cudaGetSymbolAddress((void**)&Wkvt, g_Wkvt);
    cudaGetSymbolAddress((void**)&Wot, g_Wot);

    // operand prep
    cvt_half_kernel<<<(MROWS * D_ / 2 + 255) / 256, 256>>>(x, xh, MROWS * D_ / 2);
    transpose_qo_kernel<<<dim3(D_ / 32, D_ / 32, 2), dim3(32, 8)>>>(Wq, Wo);
    transpose_wkv_kernel<<<dim3(KV_ / 32, D_ / 32, 2), dim3(32, 8)>>>(Wk, Wv, Wkvt);
    rope_table_kernel<<<T_ * 32 / 256, 256>>>();

    // Projections (fp16 tensor cores, f32 accumulate/out)
    gemm_f16<<<dim3(D_ / 128, MROWS / 128), 256, GH_SMEM_BYTES>>>(xh, Wqt, Q, D_, D_);
    gemm_f16<<<dim3(1024 / 128, MROWS / 128), 256, GH_SMEM_BYTES>>>(xh, Wkvt, KV, 1024, D_);

    // RoPE (table-based) + k norm + fp16 conversion + V transpose
    rope_q_kernel<<<MROWS, NH_ * 32>>>();
    rope_k_kernel<<<MROWS, NKV_ * 32>>>();

    // Attention (fp16 tensor cores, GQA-shared K/V)
    flash_f16_kernel<<<dim3(T_ / 64, B_ * NKV_), 256>>>();

    // Output projection
    gemm_f16<<<dim3(D_ / 128, MROWS / 128), 256, GH_SMEM_BYTES>>>(Yh, Wot, out, D_, D_);
}